// round 10
// baseline (speedup 1.0000x reference)
#include <cuda_runtime.h>
#include <cstdint>

#define TB 384
#define BT 32
#define CH 16

typedef unsigned long long u64;

struct SmemLayout {
    float P[19][BT][64];      // partial-sum planes  (152 KB)
    float x[CH][6][BT];       // x chunk             (12 KB)
    float h1[2][BT][64];      // h1 double buffer    (16 KB)
    float h2[BT][64];         // h2 state            (8 KB)
    float Wih0s[192*6];       // layer-0 input weights (4.5 KB)
};

// plane indices:
// L0: 0 r_lo, 1 z_lo, 2 hn_lo, 3 xn, 4 r_hi, 5 z_hi, 6 hn_hi
// L1: 7 ihr_lo, 8 ihz_lo, 9 ihn_lo, 10 ihr_hi, 11 ihz_hi, 12 ihn_hi,
//     13 hhr_lo, 14 hhz_lo, 15 hhn_lo, 16 hhr_hi, 17 hhz_hi, 18 hhn_hi

__device__ __forceinline__ void ffma2(u64 &acc, u64 a, u64 b){
    asm("fma.rn.f32x2 %0, %1, %2, %0;" : "+l"(acc) : "l"(a), "l"(b));
}
__device__ __forceinline__ float psum(u64 a){
    return __uint_as_float((unsigned)a) + __uint_as_float((unsigned)(a>>32));
}
__device__ __forceinline__ u64 packb(float b){ return (u64)__float_as_uint(b); }
__device__ __forceinline__ float sigf(float x){
    return __fdividef(1.0f, 1.0f + __expf(-x));
}
__device__ __forceinline__ float tanhf_fast(float x){
    return 2.0f*sigf(2.0f*x) - 1.0f;
}

__global__ __launch_bounds__(TB, 1)
void gru2_kernel(const float* __restrict__ x,
    const float* __restrict__ Wih0, const float* __restrict__ Whh0,
    const float* __restrict__ bih0, const float* __restrict__ bhh0,
    const float* __restrict__ Wih1, const float* __restrict__ Whh1,
    const float* __restrict__ bih1, const float* __restrict__ bhh1,
    const float* __restrict__ Wfc,  const float* __restrict__ bfc,
    float* __restrict__ out)
{
    extern __shared__ char smem_raw[];
    SmemLayout* S = (SmemLayout*)smem_raw;

    const int tid  = threadIdx.x;
    const int wid  = tid >> 5;
    const int lane = tid & 31;
    const int b0   = blockIdx.x * BT;

    for (int i=tid; i<2*BT*64; i+=TB) (&S->h1[0][0][0])[i] = 0.f;
    for (int i=tid; i<BT*64;   i+=TB) (&S->h2[0][0])[i]    = 0.f;
    for (int i=tid; i<192*6;   i+=TB) S->Wih0s[i] = Wih0[i];

    // ---- role decode: 12 warps = 3 roles x 2 khalf x 2 unit-halves ----
    // w0,1: L0 klo  w2,3: L0 khi  w4,5: ih klo  w6,7: ih khi  w8,9: hh klo  w10,11: hh khi
    const int role  = wid >> 2;          // 0=L0(hh0), 1=ih1, 2=hh1
    const int khalf = (wid >> 1) & 1;
    const int bw    = wid & 1;
    const int j     = bw*32 + lane;      // hidden unit 0..63
    const float* M  = (role==0) ? Whh0 : (role==1) ? Wih1 : Whh1;

    u64 w[3][16];
    #pragma unroll
    for (int r=0;r<3;r++){
        const u64* Wr = (const u64*)(M + (r*64 + j)*64 + khalf*32);
        #pragma unroll
        for (int q=0;q<16;q++) w[r][q] = Wr[q];
    }
    float br=0.f, bz=0.f, bn=0.f, bxn=0.f;
    if (khalf == 0){
        if (role==0){ br = bih0[j]+bhh0[j]; bz = bih0[64+j]+bhh0[64+j]; bn = bhh0[128+j]; }
        else if (role==1){ br = bih1[j]; bz = bih1[64+j]; bn = bih1[128+j]; }
        else { br = bhh1[j]; bz = bhh1[64+j]; bn = bhh1[128+j]; }
    }
    if (role==0) bxn = bih0[128+j];      // both khalves carry it (2 cols each)
    const int pbase = (role==0) ? (khalf?4:0) : (role==1) ? (khalf?10:7) : (khalf?16:13);
    __syncthreads();

    for (int t=0; t<=256; t++){
        const int prev = (t+1)&1;
        const int cur  = t&1;

        // ---- stage x chunk every CH steps ----
        if ((t & (CH-1)) == 0 && t < 256){
            for (int idx=tid; idx<CH*6*BT; idx+=TB){
                int c = idx / (CH*6);
                int q = idx - c*(CH*6);
                S->x[q/6][q%6][c] = x[(long)(b0+c)*(256*6) + (t + q/6)*6 + (q%6)];
            }
            __syncthreads();
        }
        const int lt = t & (CH-1);

        // ================= Phase A : dot products, 8 col-groups =================
        bool actA = (role==0) ? (t<256) : (t>=1);
        if (actA){
            const float* hsrc = (role==2) ? &S->h2[0][0] : &S->h1[prev][0][0];
            for (int g=0; g<8; g++){
                const int c0 = g*4;
                const ulonglong2* s0 = (const ulonglong2*)(hsrc + (c0+0)*64 + khalf*32);
                const ulonglong2* s1 = (const ulonglong2*)(hsrc + (c0+1)*64 + khalf*32);
                const ulonglong2* s2 = (const ulonglong2*)(hsrc + (c0+2)*64 + khalf*32);
                const ulonglong2* s3 = (const ulonglong2*)(hsrc + (c0+3)*64 + khalf*32);

                u64 acc[3][4];
                #pragma unroll
                for (int c=0;c<4;c++){
                    acc[0][c] = packb(br); acc[1][c] = packb(bz); acc[2][c] = packb(bn);
                }
                #pragma unroll
                for (int q=0;q<8;q++){
                    ulonglong2 p0=s0[q], p1=s1[q], p2=s2[q], p3=s3[q];
                    #pragma unroll
                    for (int r=0;r<3;r++){
                        u64 wa = w[r][2*q], wb = w[r][2*q+1];
                        ffma2(acc[r][0],wa,p0.x); ffma2(acc[r][1],wa,p1.x);
                        ffma2(acc[r][2],wa,p2.x); ffma2(acc[r][3],wa,p3.x);
                        ffma2(acc[r][0],wb,p0.y); ffma2(acc[r][1],wb,p1.y);
                        ffma2(acc[r][2],wb,p2.y); ffma2(acc[r][3],wb,p3.y);
                    }
                }
                float v[3][4];
                #pragma unroll
                for (int r=0;r<3;r++)
                    #pragma unroll
                    for (int c=0;c<4;c++) v[r][c] = psum(acc[r][c]);

                if (role==0){
                    // x-part: this warp covers 2 of the 4 cols (klo: 0,1; khi: 2,3)
                    const int cx = khalf*2;
                    float xn0 = bxn, xn1 = bxn;
                    #pragma unroll
                    for (int i=0;i<6;i++){
                        float xa = S->x[lt][i][c0+cx];
                        float xb = S->x[lt][i][c0+cx+1];
                        float wr = S->Wih0s[ j      *6+i];
                        float wz = S->Wih0s[(64+j) *6+i];
                        float wn = S->Wih0s[(128+j)*6+i];
                        v[0][cx]   = fmaf(wr, xa, v[0][cx]);
                        v[0][cx+1] = fmaf(wr, xb, v[0][cx+1]);
                        v[1][cx]   = fmaf(wz, xa, v[1][cx]);
                        v[1][cx+1] = fmaf(wz, xb, v[1][cx+1]);
                        xn0 = fmaf(wn, xa, xn0);
                        xn1 = fmaf(wn, xb, xn1);
                    }
                    S->P[3][c0+cx][j]   = xn0;
                    S->P[3][c0+cx+1][j] = xn1;
                }
                #pragma unroll
                for (int r=0;r<3;r++)
                    #pragma unroll
                    for (int c=0;c<4;c++) S->P[pbase+r][c0+c][j] = v[r][c];
            }
        }
        __syncthreads();   // BAR1: partials ready, h reads done

        // ================= Phase B : activations, 4096 cells over 384 lanes =================
        for (int idx = tid; idx < 4096; idx += TB){
            int layer = idx >> 11;
            int rr = idx & 2047;
            int c = rr >> 6, jj = rr & 63;
            if (layer == 0){
                if (t < 256){
                    float r  = sigf(S->P[0][c][jj] + S->P[4][c][jj]);
                    float z  = sigf(S->P[1][c][jj] + S->P[5][c][jj]);
                    float hn = S->P[2][c][jj] + S->P[6][c][jj];
                    float n  = tanhf_fast(fmaf(r, hn, S->P[3][c][jj]));
                    float hold = S->h1[prev][c][jj];
                    S->h1[cur][c][jj] = n + z*(hold - n);
                }
            } else {
                if (t >= 1){
                    float xr = S->P[7][c][jj]  + S->P[10][c][jj];
                    float xz = S->P[8][c][jj]  + S->P[11][c][jj];
                    float xn = S->P[9][c][jj]  + S->P[12][c][jj];
                    float hr = S->P[13][c][jj] + S->P[16][c][jj];
                    float hz = S->P[14][c][jj] + S->P[17][c][jj];
                    float hn = S->P[15][c][jj] + S->P[18][c][jj];
                    float r  = sigf(xr + hr);
                    float z  = sigf(xz + hz);
                    float n  = tanhf_fast(fmaf(r, hn, xn));
                    float hold = S->h2[c][jj];
                    S->h2[c][jj] = n + z*(hold - n);
                }
            }
        }
        __syncthreads();   // BAR2: h states ready
    }

    // ---- final FC ----
    if (tid < BT){
        float s = bfc[0];
        #pragma unroll
        for (int k=0;k<64;k++)
            s = fmaf(S->h2[tid][k], Wfc[k], s);
        out[b0 + tid] = s;
    }
}

extern "C" void kernel_launch(void* const* d_in, const int* in_sizes, int n_in,
                              void* d_out, int out_size)
{
    (void)in_sizes; (void)n_in; (void)out_size;
    cudaFuncSetAttribute(gru2_kernel,
                         cudaFuncAttributeMaxDynamicSharedMemorySize,
                         (int)sizeof(SmemLayout));
    gru2_kernel<<<4096/BT, TB, sizeof(SmemLayout)>>>(
        (const float*)d_in[0],
        (const float*)d_in[1], (const float*)d_in[2],
        (const float*)d_in[3], (const float*)d_in[4],
        (const float*)d_in[5], (const float*)d_in[6],
        (const float*)d_in[7], (const float*)d_in[8],
        (const float*)d_in[9], (const float*)d_in[10],
        (float*)d_out);
}